// round 14
// baseline (speedup 1.0000x reference)
#include <cuda_runtime.h>
#include <math.h>

// Problem constants (expected)
#define NLAT 361
#define NLON 720
#define MMAX 361
#define LMAX 361
#define KPAD 368            // padded contraction length (zeros in pad)
#define MCHUNK 64           // m-modes per stage1+stage2 pair

#define X_ELEMS 33269760LL  // 4*16*2*361*720
#define W_ELEMS 94091762LL  // 2*361*361*361
#define OUT_REAL 16681088LL // 4*16*2*361*361 float32 (REAL parts only)

// Static scratch: one m-chunk of stage1 output, G[mloc][t*64+bc][k] (24.1 MB)
__device__ __align__(256) float d_G[MCHUNK * 256 * KPAD];

// ---------------------------------------------------------------------------
// Zero-fill owned output region (insurance: we also fully overwrite it).
// ---------------------------------------------------------------------------
__global__ void zero_out_kernel(float* __restrict__ out, long long cap) {
    long long i = (long long)blockIdx.x * blockDim.x + threadIdx.x;
    if (i < cap) out[i] = 0.f;
}

// ---------------------------------------------------------------------------
// Stage 1 (per m-chunk): folded real DFT as GEMM, trig table in smem.
//   G[mloc][t*64+bc][k] = sum_{n=0..360} fold(x)[row][n] * T[(n*m)%720]
//   isIm=0: u[n]=x[n]+x[720-n] (u0=x0,u360=x360),  T =  C*cos
//   isIm=1: v[n]=x[n]-x[720-n] (v0=v360=0),        T = -C*sin
// grid = (6 k-tiles, 256 z=t*64+bc), block 16x16, 4x4 per thread.
// ---------------------------------------------------------------------------
__global__ __launch_bounds__(256) void stage1_kernel(const float* __restrict__ x,
                                                     int m_base,
                                                     long long x_cap) {
    __shared__ __align__(16) float trig[720];
    __shared__ __align__(16) float As[16][68];   // [n'][k]
    __shared__ __align__(16) float Bs[16][68];   // [n'][mloc]

    int z = blockIdx.y;            // t*64 + bc
    int t = z >> 6;
    int bc = z & 63;
    int pol = t >> 1;
    int isIm = t & 1;
    int k0 = blockIdx.x * 64;

    int tx = threadIdx.x, ty = threadIdx.y;
    int tid = ty * 16 + tx;

    const float C = 0.008726646259971647884618453842f;  // 2*pi/720
    for (int q = tid; q < 720; q += 256) {
        float s, c;
        sincospif((float)q * (1.0f / 360.0f), &s, &c);
        trig[q] = isIm ? (-C) * s : C * c;
    }
    __syncthreads();

    int rowbase = (bc * 2 + pol) * NLAT;

    float acc[4][4] = {};

    for (int n0 = 0; n0 < 361; n0 += 16) {
        // As tile (64 k x 16 n), folded on the fly, transposed into As[n'][k]
        {
            int kk = tid >> 2;
            int nn4 = (tid & 3) * 4;
            int krow = k0 + kk;
#pragma unroll
            for (int q = 0; q < 4; q++) {
                int n = n0 + nn4 + q;
                float val = 0.f;
                if (krow < NLAT && n < 361) {
                    long long xi = (long long)(rowbase + krow) * NLON + n;
                    float a = (xi < x_cap) ? x[xi] : 0.f;
                    if (n == 0 || n == 360) {
                        val = isIm ? 0.f : a;
                    } else {
                        long long xj = (long long)(rowbase + krow) * NLON + (NLON - n);
                        float b = (xj < x_cap) ? x[xj] : 0.f;
                        val = isIm ? (a - b) : (a + b);
                    }
                }
                As[nn4 + q][kk] = val;
            }
        }
        // Bs tile (16 n x 64 mloc) from smem trig table
        {
            int nn = tid >> 4;
            int mm4 = (tid & 15) * 4;
            int n = n0 + nn;
#pragma unroll
            for (int q = 0; q < 4; q++) {
                int mglob = m_base + mm4 + q;
                float val = 0.f;
                if (n < 361 && mglob < MMAX)
                    val = trig[(n * mglob) % 720];
                Bs[nn][mm4 + q] = val;
            }
        }
        __syncthreads();

#pragma unroll
        for (int nn = 0; nn < 16; nn++) {
            float av[4], bv[4];
#pragma unroll
            for (int i = 0; i < 4; i++) av[i] = As[nn][ty * 4 + i];
#pragma unroll
            for (int j = 0; j < 4; j++) bv[j] = Bs[nn][tx * 4 + j];
#pragma unroll
            for (int i = 0; i < 4; i++)
#pragma unroll
                for (int j = 0; j < 4; j++)
                    acc[i][j] = fmaf(av[i], bv[j], acc[i][j]);
        }
        __syncthreads();
    }

    // Write chunk-local G (k pads 361..367 get acc==0: As zeroed those rows)
#pragma unroll
    for (int i = 0; i < 4; i++) {
        int k = k0 + ty * 4 + i;
#pragma unroll
        for (int j = 0; j < 4; j++) {
            int mloc = tx * 4 + j;
            if (m_base + mloc < MMAX && k < KPAD)
                d_G[((long long)mloc * 256 + z) * KPAD + k] = acc[i][j];
        }
    }
}

// ---------------------------------------------------------------------------
// Stage 2 (per m-chunk): REAL-PART contraction with fused sign-combination.
// The harness output is float32 (4,16,2,361,361) = real parts of s,t:
//   s_re =  C(t0,w0) - C(t3,w1)   (a0*b0 - a3*b1)
//   t_re = -C(t1,w1) - C(t2,w0)   (-a1*b1 - a2*b0)
// where C(t,w)[bc][l] = sum_k G[mloc][t*64+bc][k] * weights[w][m][l][k].
// grid = (6 l-tiles, chunk m count), block 16x16, 4x4 per thread.
// ---------------------------------------------------------------------------
__global__ __launch_bounds__(256) void stage2_kernel(const float* __restrict__ w,
                                                     float* __restrict__ out,
                                                     int m_base,
                                                     long long w_cap,
                                                     long long out_cap) {
    __shared__ __align__(16) float As[16][260];      // [k'][r = t*64+bc]
    __shared__ __align__(16) float Bs[16][2][68];    // [k'][w][l]

    int mloc = blockIdx.y;
    int m = m_base + mloc;
    int l0 = blockIdx.x * 64;
    int tx = threadIdx.x, ty = threadIdx.y;
    int tid = ty * 16 + tx;

    float sre[4][4] = {}, tre[4][4] = {};

    const float* Gm = d_G + (long long)mloc * 256 * KPAD;

    for (int k0 = 0; k0 < 361; k0 += 16) {
        // All 256 G rows for this k-chunk; r = tid, 16 k each (pads are 0)
        {
            const float* gr = Gm + (long long)tid * KPAD + k0;
#pragma unroll
            for (int kk = 0; kk < 16; kk++)
                As[kk][tid] = gr[kk];
        }
        // Weight tile: 2 w-planes x 64 l x 16 k (scalar, runtime-capped)
        {
            int wsel = tid >> 7;
            int rem = tid & 127;
            int ll = rem >> 1;
            int kst = (rem & 1) * 8;
            int lg = l0 + ll;
#pragma unroll
            for (int q = 0; q < 8; q++) {
                int kk = kst + q;
                int kg = k0 + kk;
                float val = 0.f;
                if (lg < LMAX && kg < NLAT) {
                    long long wi = (((long long)wsel * MMAX + m) * LMAX + lg) * NLAT + kg;
                    if (wi < w_cap) val = w[wi];
                }
                Bs[kk][wsel][ll] = val;
            }
        }
        __syncthreads();

#pragma unroll 4
        for (int kk = 0; kk < 16; kk++) {
            float a0[4], a1[4], a2[4], a3[4], b0[4], b1[4];
#pragma unroll
            for (int i = 0; i < 4; i++) {
                a0[i] = As[kk][0 * 64 + ty * 4 + i];
                a1[i] = As[kk][1 * 64 + ty * 4 + i];
                a2[i] = As[kk][2 * 64 + ty * 4 + i];
                a3[i] = As[kk][3 * 64 + ty * 4 + i];
            }
#pragma unroll
            for (int j = 0; j < 4; j++) {
                b0[j] = Bs[kk][0][tx * 4 + j];
                b1[j] = Bs[kk][1][tx * 4 + j];
            }
#pragma unroll
            for (int i = 0; i < 4; i++) {
#pragma unroll
                for (int j = 0; j < 4; j++) {
                    sre[i][j] = fmaf(a0[i], b0[j], sre[i][j]);
                    sre[i][j] = fmaf(-a3[i], b1[j], sre[i][j]);
                    tre[i][j] = fmaf(-a1[i], b1[j], tre[i][j]);
                    tre[i][j] = fmaf(-a2[i], b0[j], tre[i][j]);
                }
            }
        }
        __syncthreads();
    }

    // Epilogue: REAL scalar writes, out[(bc,st,l,m)] float32, capped.
#pragma unroll
    for (int i = 0; i < 4; i++) {
        int bc = ty * 4 + i;
#pragma unroll
        for (int j = 0; j < 4; j++) {
            int l = l0 + tx * 4 + j;
            if (l < LMAX) {
                long long ci0 = ((long long)(bc * 2 + 0) * LMAX + l) * MMAX + m;
                long long ci1 = ((long long)(bc * 2 + 1) * LMAX + l) * MMAX + m;
                if (ci0 < out_cap) out[ci0] = sre[i][j];
                if (ci1 < out_cap) out[ci1] = tre[i][j];
            }
        }
    }
}

// ---------------------------------------------------------------------------
extern "C" void kernel_launch(void* const* d_in, const int* in_sizes, int n_in,
                              void* d_out, int out_size) {
    // Identify inputs: exact element-count match, then relative-size fallback.
    const float* x = 0;
    const float* w = 0;
    long long x_sz = 0, w_sz = 0;
    for (int i = 0; i < n_in; i++) {
        if ((long long)in_sizes[i] == X_ELEMS) { x = (const float*)d_in[i]; x_sz = in_sizes[i]; }
        else if ((long long)in_sizes[i] == W_ELEMS) { w = (const float*)d_in[i]; w_sz = in_sizes[i]; }
    }
    if ((!x || !w) && n_in >= 2) {
        int big = (in_sizes[0] >= in_sizes[1]) ? 0 : 1;
        w = (const float*)d_in[big];      w_sz = in_sizes[big];
        x = (const float*)d_in[1 - big];  x_sz = in_sizes[1 - big];
    }
    if (!x || !w) return;

    // Read caps: never exceed either reported or expected extents.
    long long x_cap = (x_sz < X_ELEMS) ? x_sz : X_ELEMS;
    long long w_cap = (w_sz < W_ELEMS) ? w_sz : W_ELEMS;

    // Output: out_size float32 elements, verbatim (R13 proved the buffer is
    // exactly out_size floats: expanding past it faults, writing to it不).
    long long out_cap = (long long)out_size;

    float* out = (float*)d_out;

    // Deterministic output across the owned region (cheap insurance; the
    // stage2 writes below cover every index < min(out_cap, OUT_REAL)).
    {
        int tpb = 256;
        long long nblk = (out_cap + tpb - 1) / tpb;
        if (nblk > 0) zero_out_kernel<<<(unsigned)nblk, tpb>>>(out, out_cap);
    }

    for (int mb = 0; mb < MMAX; mb += MCHUNK) {
        int mm = MMAX - mb;
        if (mm > MCHUNK) mm = MCHUNK;
        stage1_kernel<<<dim3(6, 256), dim3(16, 16)>>>(x, mb, x_cap);
        stage2_kernel<<<dim3(6, mm), dim3(16, 16)>>>(w, out, mb, w_cap, out_cap);
    }
}

// round 15
// speedup vs baseline: 1.4446x; 1.4446x over previous
#include <cuda_runtime.h>
#include <math.h>

// Problem constants
#define NLAT 361
#define NLON 720
#define MMAX 361
#define LMAX 361
#define NPAD 368            // padded n (DFT length after folding)
#define KPAD 368            // padded k per weight plane
#define FSTRIDE 384         // trig table row stride (m cols, padded)
#define NROWS_X 46208       // 4*16*2*361 rows of x
#define UROWS 46336         // padded rows (slack for tile overreach)

#define X_ELEMS 33269760LL  // 4*16*2*361*720
#define W_ELEMS 94091762LL  // 2*361*361*361

// Static scratch (zero-initialized at load; pads never written stay zero)
__device__ __align__(256) float d_U[(size_t)UROWS * NPAD];       // 68 MB
__device__ __align__(256) float d_V[(size_t)UROWS * NPAD];       // 68 MB
__device__ __align__(256) float d_Fc[368 * FSTRIDE];             // 0.57 MB
__device__ __align__(256) float d_Fs[368 * FSTRIDE];
__device__ __align__(256) float d_G[(size_t)MMAX * 256 * KPAD];  // 136 MB

// ---------------------------------------------------------------------------
// Prep: fold x[n] +- x[720-n] into U (cos path) / V (sin path), zero pads.
// ---------------------------------------------------------------------------
__global__ void prep_kernel(const float* __restrict__ x, long long x_cap) {
    int row = blockIdx.x;          // 0..46207
    int n = threadIdx.x;           // 0..367
    if (n >= NPAD) return;
    float u = 0.f, v = 0.f;
    if (n < 361) {
        long long base = (long long)row * NLON;
        float a = (base + n < x_cap) ? x[base + n] : 0.f;
        if (n == 0 || n == 360) {
            u = a;
        } else {
            float b = (base + NLON - n < x_cap) ? x[base + NLON - n] : 0.f;
            u = a + b;
            v = a - b;
        }
    }
    d_U[(size_t)row * NPAD + n] = u;
    d_V[(size_t)row * NPAD + n] = v;
}

// ---------------------------------------------------------------------------
// Trig tables: Fc[n][m] = C*cos(2pi n m/720), Fs = -C*sin(...); zero pads.
// ---------------------------------------------------------------------------
__global__ void trig_kernel() {
    int idx = blockIdx.x * 256 + threadIdx.x;
    if (idx >= 368 * FSTRIDE) return;
    int n = idx / FSTRIDE, m = idx % FSTRIDE;
    float fc = 0.f, fs = 0.f;
    if (n < 361 && m < 361) {
        const float C = 0.008726646259971647884618453842f;  // 2*pi/720
        int q = (int)(((long long)n * m) % 720);
        float s, c;
        sincospif((float)q * (1.0f / 360.0f), &s, &c);
        fc = C * c;
        fs = -C * s;
    }
    d_Fc[idx] = fc;
    d_Fs[idx] = fs;
}

// ---------------------------------------------------------------------------
// Stage 1: G[m][z=t*64+bc][k] = sum_n A[row(z)*361+k][n] * F[n][m]
// A = U or V, F = Fc or Fs selected by isIm = t&1; pol = t>>1.
// 128x128 tile, 256 threads, 8x8 per thread. grid (3 mtiles, 3 ktiles, 256 z)
// ---------------------------------------------------------------------------
__global__ __launch_bounds__(256, 2) void stage1_kernel() {
    __shared__ float As[16][132];   // [n'][k]  (132: STS-conflict pad, /4 ok)
    __shared__ float Bs[16][128];   // [n'][m]

    int z = blockIdx.z;
    int t = z >> 6;
    int bc = z & 63;
    int pol = t >> 1;
    int isIm = t & 1;
    int m0 = blockIdx.x * 128;
    int k0 = blockIdx.y * 128;

    const float* A = isIm ? d_V : d_U;
    const float* F = isIm ? d_Fs : d_Fc;
    long long rowbase = (long long)(bc * 2 + pol) * NLAT;

    int tid = threadIdx.x;
    int kg = tid >> 4;              // 0..15  -> k rows kg*8..+7
    int mg = tid & 15;              // 0..15  -> m cols mg*8..+7

    // A-tile loader mapping: 128 k-rows x 16 n; 2 float4 per thread
    int ar = tid >> 1;              // k row 0..127
    int ah = (tid & 1) * 8;         // n half 0 or 8
    const float* Arow = A + (rowbase + k0 + ar) * NPAD + ah;  // row < 46336
    // B-tile loader mapping: 16 n x 128 m
    int bn = tid >> 4;
    int bm = (tid & 15) * 8;

    float acc[8][8] = {};

    for (int n0 = 0; n0 < NPAD; n0 += 16) {
        float4 a0 = *(const float4*)(Arow + n0);
        float4 a1 = *(const float4*)(Arow + n0 + 4);
        As[ah + 0][ar] = a0.x; As[ah + 1][ar] = a0.y;
        As[ah + 2][ar] = a0.z; As[ah + 3][ar] = a0.w;
        As[ah + 4][ar] = a1.x; As[ah + 5][ar] = a1.y;
        As[ah + 6][ar] = a1.z; As[ah + 7][ar] = a1.w;

        const float* Fr = F + (size_t)(n0 + bn) * FSTRIDE + m0 + bm;
        *(float4*)&Bs[bn][bm] = *(const float4*)Fr;
        *(float4*)&Bs[bn][bm + 4] = *(const float4*)(Fr + 4);
        __syncthreads();

#pragma unroll
        for (int nn = 0; nn < 16; nn++) {
            float4 x0 = *(float4*)&As[nn][kg * 8];
            float4 x1 = *(float4*)&As[nn][kg * 8 + 4];
            float4 y0 = *(float4*)&Bs[nn][mg * 8];
            float4 y1 = *(float4*)&Bs[nn][mg * 8 + 4];
            float av[8] = {x0.x, x0.y, x0.z, x0.w, x1.x, x1.y, x1.z, x1.w};
            float bv[8] = {y0.x, y0.y, y0.z, y0.w, y1.x, y1.y, y1.z, y1.w};
#pragma unroll
            for (int i = 0; i < 8; i++)
#pragma unroll
                for (int j = 0; j < 8; j++)
                    acc[i][j] = fmaf(av[i], bv[j], acc[i][j]);
        }
        __syncthreads();
    }

    // Store: G[(m*256+z)*368 + k]; k in [361,368) forced to 0 (pad), k>=368 skipped
#pragma unroll
    for (int j = 0; j < 8; j++) {
        int m = m0 + mg * 8 + j;
        if (m >= MMAX) continue;
        float* gp = d_G + ((size_t)m * 256 + z) * KPAD + k0 + kg * 8;
#pragma unroll
        for (int i = 0; i < 8; i++) {
            int k = k0 + kg * 8 + i;
            if (k < KPAD) gp[i] = (k < 361) ? acc[i][j] : 0.f;
        }
    }
}

// ---------------------------------------------------------------------------
// Stage 2: per-m GEMM  D[r=st*64+bc][l] = sum_{kk<736} Ahat[r][kk]*Wstack[kk][l]
//   plane = kk>=368, kloc = kk-368*plane
//   Ahat: st0,p0:+G[t0]  st0,p1:-G[t3]  st1,p0:-G[t2]  st1,p1:-G[t1]
//   Wstack[kk][l] = w[plane][m][l][kloc]   (zeros in pads)
// Output (real parts): out[((bc*2+st)*361+l)*361+m]
// 128x128 tile, 256 threads, 8x8/thread. grid (3 ltiles, 361 m)
// ---------------------------------------------------------------------------
__global__ __launch_bounds__(256, 2) void stage2_kernel(const float* __restrict__ w,
                                                        float* __restrict__ out,
                                                        long long w_cap,
                                                        long long out_cap) {
    __shared__ float As[16][132];   // [kk'][r]
    __shared__ float Bs[16][128];   // [kk'][l]

    int m = blockIdx.y;
    int l0 = blockIdx.x * 128;
    int tid = threadIdx.x;
    int rg = tid >> 4;              // r rows rg*8..+7
    int lg = tid & 15;              // l cols lg*8..+7

    // A loader: 128 r x 16 kk
    int ar = tid >> 1;              // r 0..127
    int ah = (tid & 1) * 8;
    int ast = ar >> 6, abc = ar & 63;
    // B loader: 16 kk x 128 l
    int bl = tid >> 1;              // l 0..127
    int bh = (tid & 1) * 8;

    float acc[8][8] = {};

    for (int c = 0; c < 46; c++) {
        int kk0 = c * 16;
        int plane = (kk0 >= KPAD) ? 1 : 0;
        int kloc0 = kk0 - KPAD * plane;

        // A tile from d_G with sign folding
        {
            int tt = plane ? (ast ? 1 : 3) : (ast ? 2 : 0);
            float sgn = (ast == 0 && plane == 0) ? 1.f : -1.f;
            const float* gp = d_G + ((size_t)m * 256 + tt * 64 + abc) * KPAD + kloc0 + ah;
            float4 g0 = *(const float4*)gp;
            float4 g1 = *(const float4*)(gp + 4);
            As[ah + 0][ar] = sgn * g0.x; As[ah + 1][ar] = sgn * g0.y;
            As[ah + 2][ar] = sgn * g0.z; As[ah + 3][ar] = sgn * g0.w;
            As[ah + 4][ar] = sgn * g1.x; As[ah + 5][ar] = sgn * g1.y;
            As[ah + 6][ar] = sgn * g1.z; As[ah + 7][ar] = sgn * g1.w;
        }
        // B tile from weights (scalar, guarded; pads -> 0)
        {
            int lgl = l0 + bl;
            const float* wrow = w + (((size_t)plane * MMAX + m) * LMAX + lgl) * NLAT;
#pragma unroll
            for (int q = 0; q < 8; q++) {
                int kloc = kloc0 + bh + q;
                float val = 0.f;
                if (lgl < LMAX && kloc < NLAT) {
                    long long wi = (((long long)plane * MMAX + m) * LMAX + lgl) * NLAT + kloc;
                    if (wi < w_cap) val = wrow[kloc];
                }
                Bs[bh + q][bl] = val;
            }
        }
        __syncthreads();

#pragma unroll
        for (int nn = 0; nn < 16; nn++) {
            float4 x0 = *(float4*)&As[nn][rg * 8];
            float4 x1 = *(float4*)&As[nn][rg * 8 + 4];
            float4 y0 = *(float4*)&Bs[nn][lg * 8];
            float4 y1 = *(float4*)&Bs[nn][lg * 8 + 4];
            float av[8] = {x0.x, x0.y, x0.z, x0.w, x1.x, x1.y, x1.z, x1.w};
            float bv[8] = {y0.x, y0.y, y0.z, y0.w, y1.x, y1.y, y1.z, y1.w};
#pragma unroll
            for (int i = 0; i < 8; i++)
#pragma unroll
                for (int j = 0; j < 8; j++)
                    acc[i][j] = fmaf(av[i], bv[j], acc[i][j]);
        }
        __syncthreads();
    }

    // Epilogue: out[((bc*2+st)*361+l)*361+m]
#pragma unroll
    for (int i = 0; i < 8; i++) {
        int r = rg * 8 + i;
        int st = r >> 6, bc = r & 63;
        long long rowoff = ((long long)(bc * 2 + st) * LMAX);
#pragma unroll
        for (int j = 0; j < 8; j++) {
            int l = l0 + lg * 8 + j;
            if (l < LMAX) {
                long long oi = (rowoff + l) * MMAX + m;
                if (oi < out_cap) out[oi] = acc[i][j];
            }
        }
    }
}

// ---------------------------------------------------------------------------
extern "C" void kernel_launch(void* const* d_in, const int* in_sizes, int n_in,
                              void* d_out, int out_size) {
    // Identify inputs: exact element-count match, then relative-size fallback.
    const float* x = 0;
    const float* w = 0;
    long long x_sz = 0, w_sz = 0;
    for (int i = 0; i < n_in; i++) {
        if ((long long)in_sizes[i] == X_ELEMS) { x = (const float*)d_in[i]; x_sz = in_sizes[i]; }
        else if ((long long)in_sizes[i] == W_ELEMS) { w = (const float*)d_in[i]; w_sz = in_sizes[i]; }
    }
    if ((!x || !w) && n_in >= 2) {
        int big = (in_sizes[0] >= in_sizes[1]) ? 0 : 1;
        w = (const float*)d_in[big];      w_sz = in_sizes[big];
        x = (const float*)d_in[1 - big];  x_sz = in_sizes[1 - big];
    }
    if (!x || !w) return;

    long long x_cap = (x_sz < X_ELEMS) ? x_sz : X_ELEMS;
    long long w_cap = (w_sz < W_ELEMS) ? w_sz : W_ELEMS;
    long long out_cap = (long long)out_size;   // float32 element count (proven R13/R14)

    float* out = (float*)d_out;

    prep_kernel<<<NROWS_X, NPAD>>>(x, x_cap);
    trig_kernel<<<(368 * FSTRIDE + 255) / 256, 256>>>();
    stage1_kernel<<<dim3(3, 3, 256), 256>>>();
    stage2_kernel<<<dim3(3, MMAX), 256>>>(w, out, w_cap, out_cap);
}